// round 2
// baseline (speedup 1.0000x reference)
#include <cuda_runtime.h>
#include <cstdint>

// CrossScan: x (B=16, C=96, H=128, W=128) fp32 ->
// out (B, 4, C, H*W):
//   s=0: row-major flatten (identity)
//   s=1: HW-transposed flatten
//   s=2: s=0 reversed
//   s=3: s=1 reversed
//
// One block per (b,c). Full 128x128 fp32 tile in dynamic smem (64 KB),
// XOR-swizzled (no padding): tile4[r][c ^ (r & 31)].
//   Phase 1 STS.128: lanes vary c, r fixed -> banks c^(r&31) all distinct.
//   Phase 2 LDS.128: lanes vary h (h&31 == lane), wq fixed -> banks wq^lane distinct.

#define B_ 16
#define C_ 96
#define H_ 128
#define W_ 128
#define HW_ (H_ * W_)

__global__ __launch_bounds__(512) void cross_scan_kernel(
    const float* __restrict__ x, float* __restrict__ out)
{
    extern __shared__ float4 tile4[];   // [128][32] float4, swizzled

    const int bc = blockIdx.x;          // 0 .. B*C-1
    const int b  = bc / C_;
    const int c  = bc - b * C_;

    const int tx = threadIdx.x;         // 0..31  (lane)
    const int ty = threadIdx.y;         // 0..15

    const float* in = x + (size_t)bc * HW_;
    float* o0 = out + ((size_t)(b * 4 + 0) * C_ + c) * HW_;
    float* o1 = out + ((size_t)(b * 4 + 1) * C_ + c) * HW_;
    float* o2 = out + ((size_t)(b * 4 + 2) * C_ + c) * HW_;
    float* o3 = out + ((size_t)(b * 4 + 3) * C_ + c) * HW_;

    // ---- Phase 1: load rows, write y0 (identity) and y2 (reversed), stage smem ----
    const int wb = tx * 4;              // float column base
#pragma unroll
    for (int i = 0; i < 8; ++i) {
        const int r = ty + i * 16;      // row 0..127
        const int j = r * W_ + wb;      // flat elem index

        float4 v = __ldcs(reinterpret_cast<const float4*>(in + j));

        // y0: identity, coalesced 128B per warp
        __stcs(reinterpret_cast<float4*>(o0 + j), v);

        // y2: reversed. elems j..j+3 -> HW-1-j..HW-4-j, so write reversed
        // float4 at base HW-4-j (16B aligned: HW, r*W, 4*tx all %4==0).
        float4 rv = make_float4(v.w, v.z, v.y, v.x);
        __stcs(reinterpret_cast<float4*>(o2 + (HW_ - 4 - j)), rv);

        // stage for transpose, swizzled
        tile4[r * 32 + (tx ^ (r & 31))] = v;
    }

    __syncthreads();

    // ---- Phase 2: transposed views y1, y3 ----
    // y1[w*H + h] = x[h][w].  Thread (tx,ty) at iter (hb,half):
    //   h  = 32*hb + tx   (lane-contiguous -> coalesced 128B stores per w)
    //   wq = 16*half + ty (float4 group along w: w = 4*wq .. 4*wq+3)
#pragma unroll
    for (int hb = 0; hb < 4; ++hb) {
        const int h = 32 * hb + tx;
#pragma unroll
        for (int half = 0; half < 2; ++half) {
            const int wq = 16 * half + ty;
            float4 v = tile4[h * 32 + (wq ^ tx)];

            const int w0 = 4 * wq;
            const int i0 = (w0 + 0) * H_ + h;
            const int i1 = (w0 + 1) * H_ + h;
            const int i2 = (w0 + 2) * H_ + h;
            const int i3 = (w0 + 3) * H_ + h;

            __stcs(o1 + i0, v.x);
            __stcs(o1 + i1, v.y);
            __stcs(o1 + i2, v.z);
            __stcs(o1 + i3, v.w);

            // y3: reversed transpose; descending-contiguous per warp -> coalesced
            __stcs(o3 + (HW_ - 1 - i0), v.x);
            __stcs(o3 + (HW_ - 1 - i1), v.y);
            __stcs(o3 + (HW_ - 1 - i2), v.z);
            __stcs(o3 + (HW_ - 1 - i3), v.w);
        }
    }
}

extern "C" void kernel_launch(void* const* d_in, const int* in_sizes, int n_in,
                              void* d_out, int out_size)
{
    const float* x = (const float*)d_in[0];
    float* out = (float*)d_out;
    (void)in_sizes; (void)n_in; (void)out_size;

    const int smem = 128 * 32 * sizeof(float4);   // 64 KB
    cudaFuncSetAttribute(cross_scan_kernel,
                         cudaFuncAttributeMaxDynamicSharedMemorySize, smem);

    dim3 block(32, 16);
    cross_scan_kernel<<<B_ * C_, block, smem>>>(x, out);
}

// round 3
// speedup vs baseline: 1.0259x; 1.0259x over previous
#include <cuda_runtime.h>
#include <cstdint>

// CrossScan: x (B=16, C=96, H=128, W=128) fp32 ->
// out (B, 4, C, H*W):
//   s=0: row-major flatten (identity)
//   s=1: HW-transposed flatten
//   s=2: s=0 reversed
//   s=3: s=1 reversed
//
// Block: 32 rows (h) x 128 cols (w) of one (b,c). 256 threads, 16KB smem.
// Smem tile4[32][32] (float4), XOR-swizzled: slot = q ^ (r>>2).
//   Phase 1 STS.128 (r fixed per warp): group (tx ^ (r>>2)) mod 8 distinct. OK
//   Phase 2 LDS.128 (hi varies per 8-lane phase): group (wq ^ hi) mod 8 distinct. OK
// Phase 2 does a 4x4 register transpose so y1/y3 use STG.128.

#define B_ 16
#define C_ 96
#define H_ 128
#define W_ 128
#define HW_ (H_ * W_)

__global__ __launch_bounds__(256) void cross_scan_kernel(
    const float* __restrict__ x, float* __restrict__ out)
{
    __shared__ float4 tile4[32 * 32];   // 16 KB

    const int bc = blockIdx.y;          // 0 .. B*C-1
    const int b  = bc / C_;
    const int c  = bc - b * C_;
    const int h0 = blockIdx.x * 32;     // tile's first row

    const int tx = threadIdx.x;         // 0..31 (lane)
    const int ty = threadIdx.y;         // 0..7

    const float* in = x + (size_t)bc * HW_;
    float* o0 = out + ((size_t)(b * 4 + 0) * C_ + c) * HW_;
    float* o1 = out + ((size_t)(b * 4 + 1) * C_ + c) * HW_;
    float* o2 = out + ((size_t)(b * 4 + 2) * C_ + c) * HW_;
    float* o3 = out + ((size_t)(b * 4 + 3) * C_ + c) * HW_;

    // ---- Phase 1: load tile, write y0 (identity) + y2 (reversed), stage smem ----
    const int wb = tx * 4;              // float column base
#pragma unroll
    for (int i = 0; i < 4; ++i) {
        const int r = ty + i * 8;       // row within tile (0..31)
        const int j = (h0 + r) * W_ + wb;

        float4 v = __ldcs(reinterpret_cast<const float4*>(in + j));

        // y0: identity, coalesced
        __stcs(reinterpret_cast<float4*>(o0 + j), v);

        // y2: elems j..j+3 land at HW-1-j..HW-4-j -> reversed float4 at HW-4-j
        float4 rv = make_float4(v.w, v.z, v.y, v.x);
        __stcs(reinterpret_cast<float4*>(o2 + (HW_ - 4 - j)), rv);

        tile4[r * 32 + (tx ^ (r >> 2))] = v;
    }

    __syncthreads();

    // ---- Phase 2: transposed views y1, y3 via 4x4 register transpose ----
    // Thread (tx,ty): hi = tx&7, wi = tx>>3, wq = 4*ty + wi.
    // Covers rows r = 4*hi..4*hi+3, cols w = 4*wq..4*wq+3.
    {
        const int hi = tx & 7;
        const int wi = tx >> 3;
        const int wq = 4 * ty + wi;

        float4 r0 = tile4[(4 * hi + 0) * 32 + (wq ^ hi)];
        float4 r1 = tile4[(4 * hi + 1) * 32 + (wq ^ hi)];
        float4 r2 = tile4[(4 * hi + 2) * 32 + (wq ^ hi)];
        float4 r3 = tile4[(4 * hi + 3) * 32 + (wq ^ hi)];

        // columns: ck = x[4hi..4hi+3][4wq+k]
        float4 c0 = make_float4(r0.x, r1.x, r2.x, r3.x);
        float4 c1 = make_float4(r0.y, r1.y, r2.y, r3.y);
        float4 c2 = make_float4(r0.z, r1.z, r2.z, r3.z);
        float4 c3 = make_float4(r0.w, r1.w, r2.w, r3.w);

        const int hbase = h0 + 4 * hi;
        const int i0 = (4 * wq + 0) * H_ + hbase;
        const int i1 = (4 * wq + 1) * H_ + hbase;
        const int i2 = (4 * wq + 2) * H_ + hbase;
        const int i3 = (4 * wq + 3) * H_ + hbase;

        // y1: ascending along h, 128B per 8-lane group, coalesced
        __stcs(reinterpret_cast<float4*>(o1 + i0), c0);
        __stcs(reinterpret_cast<float4*>(o1 + i1), c1);
        __stcs(reinterpret_cast<float4*>(o1 + i2), c2);
        __stcs(reinterpret_cast<float4*>(o1 + i3), c3);

        // y3: reversed; elems i..i+3 land at HW-1-i..HW-4-i -> reversed float4
        float4 d0 = make_float4(c0.w, c0.z, c0.y, c0.x);
        float4 d1 = make_float4(c1.w, c1.z, c1.y, c1.x);
        float4 d2 = make_float4(c2.w, c2.z, c2.y, c2.x);
        float4 d3 = make_float4(c3.w, c3.z, c3.y, c3.x);
        __stcs(reinterpret_cast<float4*>(o3 + (HW_ - 4 - i0)), d0);
        __stcs(reinterpret_cast<float4*>(o3 + (HW_ - 4 - i1)), d1);
        __stcs(reinterpret_cast<float4*>(o3 + (HW_ - 4 - i2)), d2);
        __stcs(reinterpret_cast<float4*>(o3 + (HW_ - 4 - i3)), d3);
    }
}

extern "C" void kernel_launch(void* const* d_in, const int* in_sizes, int n_in,
                              void* d_out, int out_size)
{
    const float* x = (const float*)d_in[0];
    float* out = (float*)d_out;
    (void)in_sizes; (void)n_in; (void)out_size;

    dim3 block(32, 8);
    dim3 grid(H_ / 32, B_ * C_);
    cross_scan_kernel<<<grid, block>>>(x, out);
}

// round 4
// speedup vs baseline: 1.0304x; 1.0044x over previous
#include <cuda_runtime.h>
#include <cstdint>

// CrossScan: x (B=16, C=96, H=128, W=128) fp32 ->
// out (B, 4, C, H*W):
//   s=0: row-major flatten (identity)
//   s=1: HW-transposed flatten
//   s=2: s=0 reversed
//   s=3: s=1 reversed
//
// Block: 32 rows (h) x 128 cols (w) of one (b,c). 256 threads, 16KB smem.
// Smem tile4[32][32] (float4), XOR-swizzled: slot = q ^ (r>>2).
// Phase 2 does a 4x4 register transpose so y1/y3 use STG.128.
// R4 change: all output stores use st.global.wt (write-through) to avoid
// dirty-line victimization bursts in L2.

#define B_ 16
#define C_ 96
#define H_ 128
#define W_ 128
#define HW_ (H_ * W_)

__device__ __forceinline__ void stwt4(float* p, float4 v) {
    asm volatile("st.global.wt.v4.f32 [%0], {%1, %2, %3, %4};"
                 :: "l"(p), "f"(v.x), "f"(v.y), "f"(v.z), "f"(v.w)
                 : "memory");
}

__global__ __launch_bounds__(256) void cross_scan_kernel(
    const float* __restrict__ x, float* __restrict__ out)
{
    __shared__ float4 tile4[32 * 32];   // 16 KB

    const int bc = blockIdx.y;          // 0 .. B*C-1
    const int b  = bc / C_;
    const int c  = bc - b * C_;
    const int h0 = blockIdx.x * 32;     // tile's first row

    const int tx = threadIdx.x;         // 0..31 (lane)
    const int ty = threadIdx.y;         // 0..7

    const float* in = x + (size_t)bc * HW_;
    float* o0 = out + ((size_t)(b * 4 + 0) * C_ + c) * HW_;
    float* o1 = out + ((size_t)(b * 4 + 1) * C_ + c) * HW_;
    float* o2 = out + ((size_t)(b * 4 + 2) * C_ + c) * HW_;
    float* o3 = out + ((size_t)(b * 4 + 3) * C_ + c) * HW_;

    // ---- Phase 1: load tile, write y0 (identity) + y2 (reversed), stage smem ----
    const int wb = tx * 4;              // float column base
#pragma unroll
    for (int i = 0; i < 4; ++i) {
        const int r = ty + i * 8;       // row within tile (0..31)
        const int j = (h0 + r) * W_ + wb;

        float4 v = __ldcs(reinterpret_cast<const float4*>(in + j));

        // y0: identity, coalesced
        stwt4(o0 + j, v);

        // y2: elems j..j+3 land at HW-1-j..HW-4-j -> reversed float4 at HW-4-j
        float4 rv = make_float4(v.w, v.z, v.y, v.x);
        stwt4(o2 + (HW_ - 4 - j), rv);

        tile4[r * 32 + (tx ^ (r >> 2))] = v;
    }

    __syncthreads();

    // ---- Phase 2: transposed views y1, y3 via 4x4 register transpose ----
    // Thread (tx,ty): hi = tx&7, wi = tx>>3, wq = 4*ty + wi.
    // Covers rows r = 4*hi..4*hi+3, cols w = 4*wq..4*wq+3.
    {
        const int hi = tx & 7;
        const int wi = tx >> 3;
        const int wq = 4 * ty + wi;

        float4 r0 = tile4[(4 * hi + 0) * 32 + (wq ^ hi)];
        float4 r1 = tile4[(4 * hi + 1) * 32 + (wq ^ hi)];
        float4 r2 = tile4[(4 * hi + 2) * 32 + (wq ^ hi)];
        float4 r3 = tile4[(4 * hi + 3) * 32 + (wq ^ hi)];

        // columns: ck = x[4hi..4hi+3][4wq+k]
        float4 c0 = make_float4(r0.x, r1.x, r2.x, r3.x);
        float4 c1 = make_float4(r0.y, r1.y, r2.y, r3.y);
        float4 c2 = make_float4(r0.z, r1.z, r2.z, r3.z);
        float4 c3 = make_float4(r0.w, r1.w, r2.w, r3.w);

        const int hbase = h0 + 4 * hi;
        const int i0 = (4 * wq + 0) * H_ + hbase;
        const int i1 = (4 * wq + 1) * H_ + hbase;
        const int i2 = (4 * wq + 2) * H_ + hbase;
        const int i3 = (4 * wq + 3) * H_ + hbase;

        // y1: ascending along h, 128B per 8-lane group, coalesced
        stwt4(o1 + i0, c0);
        stwt4(o1 + i1, c1);
        stwt4(o1 + i2, c2);
        stwt4(o1 + i3, c3);

        // y3: reversed; elems i..i+3 land at HW-1-i..HW-4-i -> reversed float4
        float4 d0 = make_float4(c0.w, c0.z, c0.y, c0.x);
        float4 d1 = make_float4(c1.w, c1.z, c1.y, c1.x);
        float4 d2 = make_float4(c2.w, c2.z, c2.y, c2.x);
        float4 d3 = make_float4(c3.w, c3.z, c3.y, c3.x);
        stwt4(o3 + (HW_ - 4 - i0), d0);
        stwt4(o3 + (HW_ - 4 - i1), d1);
        stwt4(o3 + (HW_ - 4 - i2), d2);
        stwt4(o3 + (HW_ - 4 - i3), d3);
    }
}

extern "C" void kernel_launch(void* const* d_in, const int* in_sizes, int n_in,
                              void* d_out, int out_size)
{
    const float* x = (const float*)d_in[0];
    float* out = (float*)d_out;
    (void)in_sizes; (void)n_in; (void)out_size;

    dim3 block(32, 8);
    dim3 grid(H_ / 32, B_ * C_);
    cross_scan_kernel<<<grid, block>>>(x, out);
}